// round 8
// baseline (speedup 1.0000x reference)
#include <cuda_runtime.h>
#include <cuda_bf16.h>
#include <cstdint>

#define DFEAT 128
#define MAX_NODES 100000
#define MAX_EDGES 650000
#define SCAN_BLK 1024

// scratch (static __device__ arrays — no allocations allowed)
__device__ int    g_is64;
__device__ int    g_deg[MAX_NODES];
__device__ int    g_off[MAX_NODES];
__device__ int    g_bsum[128];
__device__ float  g_dinv[MAX_NODES];
__device__ int    g_adj[2 * MAX_EDGES];
__device__ float4 g_tmp4[(size_t)MAX_NODES * (DFEAT / 4)];

// ---------------------------------------------------------------------------
// f32x2 packed-math helpers (Blackwell; ptxas never auto-fuses these)
// ---------------------------------------------------------------------------
__device__ __forceinline__ unsigned long long dup_f32(float f) {
    unsigned long long r;
    asm("mov.b64 %0, {%1, %1};" : "=l"(r) : "f"(f));
    return r;
}
__device__ __forceinline__ float2 unpack_f32x2(unsigned long long v) {
    float2 r;
    asm("mov.b64 {%0, %1}, %2;" : "=f"(r.x), "=f"(r.y) : "l"(v));
    return r;
}
__device__ __forceinline__ unsigned long long fma2(unsigned long long a,
                                                   unsigned long long b,
                                                   unsigned long long c) {
    unsigned long long d;
    asm("fma.rn.f32x2 %0, %1, %2, %3;" : "=l"(d) : "l"(a), "l"(b), "l"(c));
    return d;
}

// ---------------------------------------------------------------------------
// Kernel 1 (fused): detect edge_index dtype + zero degree counters
// ---------------------------------------------------------------------------
__global__ void k_pre(const int* __restrict__ ei_w, int n) {
    int i = blockIdx.x * blockDim.x + threadIdx.x;
    if (i < n) g_deg[i] = 0;
    if (blockIdx.x == 0 && threadIdx.x < 32) {
        int lane = threadIdx.x;
        int z = 0;
        if (ei_w[2 * lane + 1] == 0) z++;
        if (ei_w[2 * (lane + 32) + 1] == 0) z++;
#pragma unroll
        for (int o = 16; o > 0; o >>= 1)
            z += __shfl_down_sync(0xffffffffu, z, o);
        if (lane == 0) g_is64 = (z >= 60) ? 1 : 0;
    }
}

// ---------------------------------------------------------------------------
// Kernel 2: degree histogram (both endpoints)
// ---------------------------------------------------------------------------
__global__ void k_deg(const int* __restrict__ ei_w, int E) {
    int i = blockIdx.x * blockDim.x + threadIdx.x;
    if (i < E) {
        int stride = g_is64 ? 2 : 1;
        int s = ei_w[(size_t)i * stride];
        int d = ei_w[(size_t)(E + i) * stride];
        atomicAdd(&g_deg[s], 1);
        atomicAdd(&g_deg[d], 1);
    }
}

// ---------------------------------------------------------------------------
// Kernel 3a: per-block exclusive scan (shuffle-based) + fused dinv
// ---------------------------------------------------------------------------
__global__ void k_scan1(int n) {
    __shared__ int ws[32];
    int tid  = threadIdx.x;
    int lane = tid & 31, wid = tid >> 5;
    int i = blockIdx.x * SCAN_BLK + tid;
    int v = (i < n) ? g_deg[i] : 0;

    int s = v;
#pragma unroll
    for (int o = 1; o < 32; o <<= 1) {
        int t = __shfl_up_sync(0xffffffffu, s, o);
        if (lane >= o) s += t;
    }
    if (lane == 31) ws[wid] = s;
    __syncthreads();
    if (wid == 0) {
        int t = ws[lane];
        int ss = t;
#pragma unroll
        for (int o = 1; o < 32; o <<= 1) {
            int u = __shfl_up_sync(0xffffffffu, ss, o);
            if (lane >= o) ss += u;
        }
        ws[lane] = ss - t;
    }
    __syncthreads();
    int excl = ws[wid] + s - v;
    if (i < n) {
        g_off[i]  = excl;
        g_dinv[i] = (v > 0) ? rsqrtf((float)v) : 0.0f;
    }
    if (tid == SCAN_BLK - 1) g_bsum[blockIdx.x] = excl + v;
}

// ---------------------------------------------------------------------------
// Kernel 3b: exclusive scan of block sums
// ---------------------------------------------------------------------------
__global__ void k_scan2(int nb) {
    __shared__ int sm[128];
    int tid = threadIdx.x;
    int v = (tid < nb) ? g_bsum[tid] : 0;
    sm[tid] = v;
    __syncthreads();
#pragma unroll
    for (int off = 1; off < 128; off <<= 1) {
        int t = (tid >= off) ? sm[tid - off] : 0;
        __syncthreads();
        sm[tid] += t;
        __syncthreads();
    }
    if (tid < nb) g_bsum[tid] = sm[tid] - v;
}

// ---------------------------------------------------------------------------
// Kernel 3c: add block offsets (g_off becomes the scatter cursor)
// ---------------------------------------------------------------------------
__global__ void k_scan3(int n) {
    int i = blockIdx.x * blockDim.x + threadIdx.x;
    if (i < n) g_off[i] += g_bsum[i >> 10];
}

// ---------------------------------------------------------------------------
// Kernel 4: scatter neighbor ids into CSR adjacency (advances g_off by deg;
// gather recovers base = g_off - g_deg)
// ---------------------------------------------------------------------------
__global__ void k_scatter(const int* __restrict__ ei_w, int E) {
    int i = blockIdx.x * blockDim.x + threadIdx.x;
    if (i < E) {
        int stride = g_is64 ? 2 : 1;
        int s = ei_w[(size_t)i * stride];
        int d = ei_w[(size_t)(E + i) * stride];
        int ps = atomicAdd(&g_off[s], 1);
        g_adj[ps] = d;
        int pd = atomicAdd(&g_off[d], 1);
        g_adj[pd] = s;
    }
}

// ---------------------------------------------------------------------------
// Kernel 5: gather aggregation, warp per node, 4-edge unroll.
// h[v] = x[v] + dinv[v] * sum_nb dinv[nb] * x[nb]
// ---------------------------------------------------------------------------
__global__ void k_gather(const float4* __restrict__ x4, int n) {
    int v    = (blockIdx.x * blockDim.x + threadIdx.x) >> 5;
    int lane = threadIdx.x & 31;
    if (v >= n) return;

    int deg  = g_deg[v];
    int base = g_off[v] - deg;

    float4 acc = make_float4(0.f, 0.f, 0.f, 0.f);
    int e = 0;
    int deg4 = deg & ~3;
    for (; e < deg4; e += 4) {
        int nb0 = __ldg(&g_adj[base + e]);
        int nb1 = __ldg(&g_adj[base + e + 1]);
        int nb2 = __ldg(&g_adj[base + e + 2]);
        int nb3 = __ldg(&g_adj[base + e + 3]);
        float w0 = __ldg(&g_dinv[nb0]);
        float w1 = __ldg(&g_dinv[nb1]);
        float w2 = __ldg(&g_dinv[nb2]);
        float w3 = __ldg(&g_dinv[nb3]);
        float4 v0 = __ldg(x4 + (size_t)nb0 * 32 + lane);
        float4 v1 = __ldg(x4 + (size_t)nb1 * 32 + lane);
        float4 v2 = __ldg(x4 + (size_t)nb2 * 32 + lane);
        float4 v3 = __ldg(x4 + (size_t)nb3 * 32 + lane);
        acc.x += w0 * v0.x + w1 * v1.x + w2 * v2.x + w3 * v3.x;
        acc.y += w0 * v0.y + w1 * v1.y + w2 * v2.y + w3 * v3.y;
        acc.z += w0 * v0.z + w1 * v1.z + w2 * v2.z + w3 * v3.z;
        acc.w += w0 * v0.w + w1 * v1.w + w2 * v2.w + w3 * v3.w;
    }
    for (; e < deg; e++) {
        int nb = __ldg(&g_adj[base + e]);
        float w = __ldg(&g_dinv[nb]);
        float4 vv = __ldg(x4 + (size_t)nb * 32 + lane);
        acc.x += w * vv.x; acc.y += w * vv.y;
        acc.z += w * vv.z; acc.w += w * vv.w;
    }

    float dv = g_dinv[v];
    float4 xv = __ldg(x4 + (size_t)v * 32 + lane);
    float4 h;
    h.x = xv.x + dv * acc.x;
    h.y = xv.y + dv * acc.y;
    h.z = xv.z + dv * acc.z;
    h.w = xv.w + dv * acc.w;
    g_tmp4[(size_t)v * 32 + lane] = h;
}

// ---------------------------------------------------------------------------
// Kernel 6: out = relu(h @ W^T + b) using packed f32x2 FMA.
// 256 threads, 64 rows/block, full N=128. Per thread: 8 rows x 4 cols
// (= 8x2 f32x2 accumulators). Activations stored DUPLICATED in smem
// ({a,a} 64-bit words) so the inner loop needs zero packing movs:
// per k per thread: 8x LDS.64 (broadcast) + 1x LDS.128 (W pair) + 16 FMA2.
// smem = 64*128*8 (xs2) + 32*132*4 (wt chunk) = 82432 B -> 2 CTAs/SM.
// ---------------------------------------------------------------------------
#define WT_STRIDE 132
#define KCHUNK 32
#define GROWS 64
#define GEMM_SMEM (GROWS * 128 * 8 + KCHUNK * WT_STRIDE * 4)

__global__ __launch_bounds__(256)
void k_gemm_f32x2(const float* __restrict__ W, const float* __restrict__ b,
                  float* __restrict__ out, int n) {
    extern __shared__ char smraw[];
    unsigned long long* xs2 = (unsigned long long*)smraw;        // [64][128]
    float* wt = (float*)(smraw + GROWS * 128 * 8);               // [KCHUNK][WT_STRIDE]

    int tid = threadIdx.x;
    int row0 = blockIdx.x * GROWS;

    // Load 64 rows of h, duplicated into {a,a} 64-bit words.
    for (int i = tid; i < GROWS * 32; i += 256) {
        int r = i >> 5, f = i & 31;
        float4 v = make_float4(0.f, 0.f, 0.f, 0.f);
        if (row0 + r < n) v = g_tmp4[(size_t)(row0 + r) * 32 + f];
        int k = f * 4;
        unsigned long long* p = xs2 + r * 128 + k;
        p[0] = dup_f32(v.x);
        p[1] = dup_f32(v.y);
        p[2] = dup_f32(v.z);
        p[3] = dup_f32(v.w);
    }

    int r0 = (tid >> 5) * 8;      // warp-uniform row group
    int c0 = (tid & 31) * 4;      // 4 output cols per thread

    unsigned long long acc[8][2];
    unsigned long long z = dup_f32(0.0f);
#pragma unroll
    for (int r = 0; r < 8; r++) { acc[r][0] = z; acc[r][1] = z; }

    for (int k0 = 0; k0 < 128; k0 += KCHUNK) {
        __syncthreads();
        // W chunk transposed into smem: wt[kk][j] = W[j][k0+kk]
        for (int i = tid; i < 128 * KCHUNK; i += 256) {
            int j  = i >> 5;              // output 0..127
            int kk = i & (KCHUNK - 1);
            wt[kk * WT_STRIDE + j] = W[j * 128 + k0 + kk];
        }
        __syncthreads();

#pragma unroll 8
        for (int kk = 0; kk < KCHUNK; kk++) {
            unsigned long long ap[8];
            const unsigned long long* xr = xs2 + (k0 + kk);
#pragma unroll
            for (int r = 0; r < 8; r++) ap[r] = xr[(r0 + r) * 128];
            longlong2 wv = *(const longlong2*)(wt + kk * WT_STRIDE + c0);
            unsigned long long w0 = (unsigned long long)wv.x;
            unsigned long long w1 = (unsigned long long)wv.y;
#pragma unroll
            for (int r = 0; r < 8; r++) {
                acc[r][0] = fma2(ap[r], w0, acc[r][0]);
                acc[r][1] = fma2(ap[r], w1, acc[r][1]);
            }
        }
    }

    float4 bv = *(const float4*)(b + c0);
#pragma unroll
    for (int r = 0; r < 8; r++) {
        int row = row0 + r0 + r;
        if (row < n) {
            float2 p0 = unpack_f32x2(acc[r][0]);
            float2 p1 = unpack_f32x2(acc[r][1]);
            float4 o;
            o.x = fmaxf(p0.x + bv.x, 0.0f);
            o.y = fmaxf(p0.y + bv.y, 0.0f);
            o.z = fmaxf(p1.x + bv.z, 0.0f);
            o.w = fmaxf(p1.y + bv.w, 0.0f);
            *(float4*)(out + (size_t)row * DFEAT + c0) = o;
        }
    }
}

// ---------------------------------------------------------------------------
// kernel_launch
// inputs: 0=x [N,128] f32, 1=edge_index [2,E] int32/int64, 2=W [128,128], 3=b [128]
// ---------------------------------------------------------------------------
extern "C" void kernel_launch(void* const* d_in, const int* in_sizes, int n_in,
                              void* d_out, int out_size) {
    const float* x    = (const float*)d_in[0];
    const int*   ei_w = (const int*)d_in[1];
    const float* W    = (const float*)d_in[2];
    const float* b    = (const float*)d_in[3];
    float*       out  = (float*)d_out;

    int n = in_sizes[0] / DFEAT;
    int E = in_sizes[1] / 2;
    int nb = (n + SCAN_BLK - 1) / SCAN_BLK;

    k_pre<<<(n + 255) / 256, 256>>>(ei_w, n);
    k_deg<<<(E + 255) / 256, 256>>>(ei_w, E);
    k_scan1<<<nb, SCAN_BLK>>>(n);
    k_scan2<<<1, 128>>>(nb);
    k_scan3<<<(n + 255) / 256, 256>>>(n);
    k_scatter<<<(E + 255) / 256, 256>>>(ei_w, E);
    {
        long long tthreads = (long long)n * 32;
        int blocks = (int)((tthreads + 255) / 256);
        k_gather<<<blocks, 256>>>((const float4*)x, n);
    }
    {
        cudaFuncSetAttribute(k_gemm_f32x2,
                             cudaFuncAttributeMaxDynamicSharedMemorySize,
                             GEMM_SMEM);
        k_gemm_f32x2<<<(n + GROWS - 1) / GROWS, 256, GEMM_SMEM>>>(W, b, out, n);
    }
}

// round 9
// speedup vs baseline: 1.0907x; 1.0907x over previous
#include <cuda_runtime.h>
#include <cuda_bf16.h>
#include <cstdint>

#define DFEAT 128
#define MAX_NODES 100000
#define MAX_EDGES 650000
#define BLD_BLK 1024
#define MAX_BLD 128

// scratch (static __device__ arrays — no allocations allowed)
__device__ int             g_deg[MAX_NODES];
__device__ int             g_off[MAX_NODES];
__device__ float           g_dinv[MAX_NODES];
__device__ int             g_adj[2 * MAX_EDGES];
__device__ float4          g_tmp4[(size_t)MAX_NODES * (DFEAT / 4)];
// persistent-kernel sync state; statically zero, re-zeroed by k_gemm each launch
__device__ volatile int    g_sctr[4];
__device__ volatile int    g_flag[MAX_BLD];
__device__ volatile int    g_aggr[MAX_BLD];
__device__ int             g_is64;

// ---------------------------------------------------------------------------
// Grid sync via atomic counter + spin. SAFE only because all `nb` blocks are
// co-resident (nb <= 98 < 148 SMs, 1 block/SM guaranteed by size).
// ---------------------------------------------------------------------------
__device__ __forceinline__ void grid_sync(int k, int nb) {
    __syncthreads();
    if (threadIdx.x == 0) {
        __threadfence();
        atomicAdd((int*)&g_sctr[k], 1);
        while (g_sctr[k] < nb) { }
        __threadfence();
    }
    __syncthreads();
}

// ---------------------------------------------------------------------------
// Kernel 1 (fused persistent): zero+detect -> histogram -> scan(+dinv) -> scatter
// nb blocks of 1024 threads, all co-resident.
// ---------------------------------------------------------------------------
__global__ __launch_bounds__(BLD_BLK)
void k_build(const int* __restrict__ ei_w, int n, int E, int nb) {
    __shared__ int ws[32];
    __shared__ int sbase;
    int tid  = threadIdx.x;
    int bid  = blockIdx.x;
    int lane = tid & 31, wid = tid >> 5;
    int gtid = bid * BLD_BLK + tid;
    int nthr = nb * BLD_BLK;

    // phase 0: zero degree counters; block 0 detects edge_index dtype
    for (int i = gtid; i < n; i += nthr) g_deg[i] = 0;
    if (bid == 0 && tid < 32) {
        int z = 0;
        if (ei_w[2 * tid + 1] == 0) z++;
        if (ei_w[2 * (tid + 32) + 1] == 0) z++;
#pragma unroll
        for (int o = 16; o > 0; o >>= 1)
            z += __shfl_down_sync(0xffffffffu, z, o);
        if (tid == 0) g_is64 = (z >= 60) ? 1 : 0;
    }
    grid_sync(0, nb);

    // phase 1: degree histogram
    int stride = g_is64 ? 2 : 1;
    for (int i = gtid; i < E; i += nthr) {
        int s = ei_w[(size_t)i * stride];
        int d = ei_w[(size_t)(E + i) * stride];
        atomicAdd(&g_deg[s], 1);
        atomicAdd(&g_deg[d], 1);
    }
    grid_sync(1, nb);

    // phase 2: exclusive scan of degrees (block-local + decoupled lookback)
    int i = bid * BLD_BLK + tid;
    int v = (i < n) ? g_deg[i] : 0;
    int s = v;
#pragma unroll
    for (int o = 1; o < 32; o <<= 1) {
        int t = __shfl_up_sync(0xffffffffu, s, o);
        if (lane >= o) s += t;
    }
    if (lane == 31) ws[wid] = s;
    __syncthreads();
    if (wid == 0) {
        int t = ws[lane];
        int ss = t;
#pragma unroll
        for (int o = 1; o < 32; o <<= 1) {
            int u = __shfl_up_sync(0xffffffffu, ss, o);
            if (lane >= o) ss += u;
        }
        ws[lane] = ss - t;
    }
    __syncthreads();
    int excl = ws[wid] + s - v;          // block-local exclusive prefix
    if (tid == BLD_BLK - 1) {            // publish block aggregate
        g_aggr[bid] = excl + v;
        __threadfence();
        g_flag[bid] = 1;
    }
    if (wid == 0) {                      // lookback over earlier blocks
        int base = 0;
        for (int j = lane; j < bid; j += 32) {
            while (g_flag[j] == 0) { }
            base += g_aggr[j];
        }
#pragma unroll
        for (int o = 16; o > 0; o >>= 1)
            base += __shfl_down_sync(0xffffffffu, base, o);
        if (lane == 0) sbase = base;
    }
    __syncthreads();
    if (i < n) {
        g_off[i]  = sbase + excl;
        g_dinv[i] = (v > 0) ? rsqrtf((float)v) : 0.0f;
    }
    grid_sync(2, nb);

    // phase 3: scatter neighbor ids (advances g_off; gather uses off - deg)
    for (int e = gtid; e < E; e += nthr) {
        int sN = ei_w[(size_t)e * stride];
        int dN = ei_w[(size_t)(E + e) * stride];
        int ps = atomicAdd(&g_off[sN], 1);
        g_adj[ps] = dN;
        int pd = atomicAdd(&g_off[dN], 1);
        g_adj[pd] = sN;
    }
}

// ---------------------------------------------------------------------------
// Kernel 2: gather aggregation, warp per node, 4-edge unroll.
// h[v] = x[v] + dinv[v] * sum_nb dinv[nb] * x[nb]
// ---------------------------------------------------------------------------
__global__ void k_gather(const float4* __restrict__ x4, int n) {
    int v    = (blockIdx.x * blockDim.x + threadIdx.x) >> 5;
    int lane = threadIdx.x & 31;
    if (v >= n) return;

    int deg  = g_deg[v];
    int base = g_off[v] - deg;

    float4 acc = make_float4(0.f, 0.f, 0.f, 0.f);
    int e = 0;
    int deg4 = deg & ~3;
    for (; e < deg4; e += 4) {
        int nb0 = __ldg(&g_adj[base + e]);
        int nb1 = __ldg(&g_adj[base + e + 1]);
        int nb2 = __ldg(&g_adj[base + e + 2]);
        int nb3 = __ldg(&g_adj[base + e + 3]);
        float w0 = __ldg(&g_dinv[nb0]);
        float w1 = __ldg(&g_dinv[nb1]);
        float w2 = __ldg(&g_dinv[nb2]);
        float w3 = __ldg(&g_dinv[nb3]);
        float4 v0 = __ldg(x4 + (size_t)nb0 * 32 + lane);
        float4 v1 = __ldg(x4 + (size_t)nb1 * 32 + lane);
        float4 v2 = __ldg(x4 + (size_t)nb2 * 32 + lane);
        float4 v3 = __ldg(x4 + (size_t)nb3 * 32 + lane);
        acc.x += w0 * v0.x + w1 * v1.x + w2 * v2.x + w3 * v3.x;
        acc.y += w0 * v0.y + w1 * v1.y + w2 * v2.y + w3 * v3.y;
        acc.z += w0 * v0.z + w1 * v1.z + w2 * v2.z + w3 * v3.z;
        acc.w += w0 * v0.w + w1 * v1.w + w2 * v2.w + w3 * v3.w;
    }
    for (; e < deg; e++) {
        int nb = __ldg(&g_adj[base + e]);
        float w = __ldg(&g_dinv[nb]);
        float4 vv = __ldg(x4 + (size_t)nb * 32 + lane);
        acc.x += w * vv.x; acc.y += w * vv.y;
        acc.z += w * vv.z; acc.w += w * vv.w;
    }

    float dv = g_dinv[v];
    float4 xv = __ldg(x4 + (size_t)v * 32 + lane);
    float4 h;
    h.x = xv.x + dv * acc.x;
    h.y = xv.y + dv * acc.y;
    h.z = xv.z + dv * acc.z;
    h.w = xv.w + dv * acc.w;
    g_tmp4[(size_t)v * 32 + lane] = h;
}

// ---------------------------------------------------------------------------
// Kernel 3: out = relu(h @ W^T + b)  (round-5 SIMT version, known-good)
// 256 threads, 64 rows/block, 8x4 register tile, KCHUNK=16, smem 41216 B.
// Also resets persistent-sync state for the next graph replay.
// ---------------------------------------------------------------------------
#define WT_STRIDE 132
#define KCHUNK 16
#define GROWS 64
#define GEMM_SMEM ((KCHUNK * WT_STRIDE + GROWS * 128) * 4)

__global__ __launch_bounds__(256)
void k_gemm_relu(const float* __restrict__ W,
                 const float* __restrict__ b,
                 float* __restrict__ out, int n) {
    extern __shared__ float sm[];
    float* wt = sm;                       // [KCHUNK][WT_STRIDE]
    float* xs = sm + KCHUNK * WT_STRIDE;  // [GROWS][128]

    int tid = threadIdx.x;
    int row0 = blockIdx.x * GROWS;

    // reset fused-kernel sync state for the next launch (deterministic)
    if (blockIdx.x == 0 && tid < MAX_BLD) {
        if (tid < 4) g_sctr[tid] = 0;
        g_flag[tid] = 0;
    }

    // Load up to 64 rows of aggregated features.
    {
        const float4* srcp = g_tmp4 + (size_t)row0 * 32;
        float4* dstp = (float4*)xs;
        int lim4 = (n - row0) * (DFEAT / 4);
        if (lim4 > GROWS * 32) lim4 = GROWS * 32;
        for (int i = tid; i < lim4; i += 256) dstp[i] = srcp[i];
    }

    int rg = tid >> 5;
    int cg = tid & 31;
    int r0 = rg * 8, c0 = cg * 4;

    float acc[8][4];
#pragma unroll
    for (int r = 0; r < 8; r++)
#pragma unroll
        for (int c = 0; c < 4; c++) acc[r][c] = 0.0f;

    for (int k0 = 0; k0 < 128; k0 += KCHUNK) {
        __syncthreads();
        for (int i = tid; i < 128 * KCHUNK; i += 256) {
            int j  = i >> 4;
            int kk = i & (KCHUNK - 1);
            wt[kk * WT_STRIDE + j] = W[j * 128 + k0 + kk];
        }
        __syncthreads();

#pragma unroll
        for (int kk = 0; kk < KCHUNK; kk++) {
            int k = k0 + kk;
            float4 wv = *(const float4*)(wt + kk * WT_STRIDE + c0);
#pragma unroll
            for (int r = 0; r < 8; r++) {
                float a = xs[(r0 + r) * 128 + k];
                acc[r][0] += a * wv.x;
                acc[r][1] += a * wv.y;
                acc[r][2] += a * wv.z;
                acc[r][3] += a * wv.w;
            }
        }
    }

    float4 bv = *(const float4*)(b + c0);
#pragma unroll
    for (int r = 0; r < 8; r++) {
        int row = row0 + r0 + r;
        if (row < n) {
            float4 o;
            o.x = fmaxf(acc[r][0] + bv.x, 0.0f);
            o.y = fmaxf(acc[r][1] + bv.y, 0.0f);
            o.z = fmaxf(acc[r][2] + bv.z, 0.0f);
            o.w = fmaxf(acc[r][3] + bv.w, 0.0f);
            *(float4*)(out + (size_t)row * DFEAT + c0) = o;
        }
    }
}

// ---------------------------------------------------------------------------
// kernel_launch
// inputs: 0=x [N,128] f32, 1=edge_index [2,E] int32/int64, 2=W [128,128], 3=b [128]
// ---------------------------------------------------------------------------
extern "C" void kernel_launch(void* const* d_in, const int* in_sizes, int n_in,
                              void* d_out, int out_size) {
    const float* x    = (const float*)d_in[0];
    const int*   ei_w = (const int*)d_in[1];
    const float* W    = (const float*)d_in[2];
    const float* b    = (const float*)d_in[3];
    float*       out  = (float*)d_out;

    int n = in_sizes[0] / DFEAT;
    int E = in_sizes[1] / 2;
    int nb = (n + BLD_BLK - 1) / BLD_BLK;   // 98 for n=100000 (co-resident)
    if (nb > MAX_BLD) nb = MAX_BLD;

    k_build<<<nb, BLD_BLK>>>(ei_w, n, E, nb);
    {
        long long tthreads = (long long)n * 32;
        int blocks = (int)((tthreads + 255) / 256);
        k_gather<<<blocks, 256>>>((const float4*)x, n);
    }
    k_gemm_relu<<<(n + GROWS - 1) / GROWS, 256, GEMM_SMEM>>>(W, b, out, n);
}

// round 10
// speedup vs baseline: 1.1589x; 1.0625x over previous
#include <cuda_runtime.h>
#include <cuda_bf16.h>
#include <cstdint>

#define DFEAT 128
#define MAX_NODES 100000
#define MAX_EDGES 650000
#define BLD_BLK 512
#define BLD_NB  444          // 3 blocks/SM on 148 SMs; all co-resident
#define MAX_BLD 512

// scratch (static __device__ arrays — no allocations allowed)
__device__ int          g_deg[MAX_NODES];
__device__ int          g_off[MAX_NODES];
__device__ float        g_dinv[MAX_NODES];
__device__ int          g_adj[2 * MAX_EDGES];
// persistent-kernel sync state; statically zero, re-zeroed by k_gg each launch
__device__ volatile int g_sctr[4];
__device__ volatile int g_flag[MAX_BLD];
__device__ volatile int g_aggr[MAX_BLD];
__device__ int          g_is64;

// ---------------------------------------------------------------------------
// Grid sync via atomic counter + spin. SAFE only because all BLD_NB blocks
// are co-resident (444 = 3/SM, 512 thr, ~32 regs -> fits).
// ---------------------------------------------------------------------------
__device__ __forceinline__ void grid_sync(int k, int nb) {
    __syncthreads();
    if (threadIdx.x == 0) {
        __threadfence();
        atomicAdd((int*)&g_sctr[k], 1);
        while (g_sctr[k] < nb) { }
        __threadfence();
    }
    __syncthreads();
}

// ---------------------------------------------------------------------------
// Kernel 1 (fused persistent): zero+detect -> histogram -> scan(+dinv) -> scatter
// ---------------------------------------------------------------------------
__global__ __launch_bounds__(BLD_BLK)
void k_build(const int* __restrict__ ei_w, int n, int E, int nb) {
    __shared__ int ws[16];
    __shared__ int sbase;
    int tid  = threadIdx.x;
    int bid  = blockIdx.x;
    int lane = tid & 31, wid = tid >> 5;
    int gtid = bid * BLD_BLK + tid;
    int nthr = nb * BLD_BLK;

    // phase 0: zero degree counters; block 0 detects edge_index dtype
    for (int i = gtid; i < n; i += nthr) g_deg[i] = 0;
    if (bid == 0 && tid < 32) {
        int z = 0;
        if (ei_w[2 * tid + 1] == 0) z++;
        if (ei_w[2 * (tid + 32) + 1] == 0) z++;
#pragma unroll
        for (int o = 16; o > 0; o >>= 1)
            z += __shfl_down_sync(0xffffffffu, z, o);
        if (tid == 0) g_is64 = (z >= 60) ? 1 : 0;
    }
    grid_sync(0, nb);

    // phase 1: degree histogram
    int stride = g_is64 ? 2 : 1;
    for (int i = gtid; i < E; i += nthr) {
        int s = ei_w[(size_t)i * stride];
        int d = ei_w[(size_t)(E + i) * stride];
        atomicAdd(&g_deg[s], 1);
        atomicAdd(&g_deg[d], 1);
    }
    grid_sync(1, nb);

    // phase 2: exclusive scan of degrees (block-local + lookback)
    int i = gtid;
    int v = (i < n) ? g_deg[i] : 0;
    int s = v;
#pragma unroll
    for (int o = 1; o < 32; o <<= 1) {
        int t = __shfl_up_sync(0xffffffffu, s, o);
        if (lane >= o) s += t;
    }
    if (lane == 31) ws[wid] = s;
    __syncthreads();
    if (wid == 0 && lane < 16) {
        int t = ws[lane];
        int ss = t;
#pragma unroll
        for (int o = 1; o < 16; o <<= 1) {
            int u = __shfl_up_sync(0x0000ffffu, ss, o);
            if (lane >= o) ss += u;
        }
        ws[lane] = ss - t;
    }
    __syncthreads();
    int excl = ws[wid] + s - v;          // block-local exclusive prefix
    if (tid == BLD_BLK - 1) {            // publish block aggregate
        g_aggr[bid] = excl + v;
        __threadfence();
        g_flag[bid] = 1;
    }
    if (wid == 0) {                      // lookback over earlier blocks
        int base = 0;
        for (int j = lane; j < bid; j += 32) {
            while (g_flag[j] == 0) { }
            base += g_aggr[j];
        }
#pragma unroll
        for (int o = 16; o > 0; o >>= 1)
            base += __shfl_down_sync(0xffffffffu, base, o);
        if (lane == 0) sbase = base;
    }
    __syncthreads();
    if (i < n) {
        g_off[i]  = sbase + excl;
        g_dinv[i] = (v > 0) ? rsqrtf((float)v) : 0.0f;
    }
    grid_sync(2, nb);

    // phase 3: scatter neighbor ids (advances g_off; consumer uses off - deg)
    for (int e = gtid; e < E; e += nthr) {
        int sN = ei_w[(size_t)e * stride];
        int dN = ei_w[(size_t)(E + e) * stride];
        int ps = atomicAdd(&g_off[sN], 1);
        g_adj[ps] = dN;
        int pd = atomicAdd(&g_off[dN], 1);
        g_adj[pd] = sN;
    }
}

// ---------------------------------------------------------------------------
// Kernel 2 (fused): gather aggregation directly into smem tile, then
// out = relu(h @ W^T + b). 256 threads, 64 rows/block.
// Gather: warp w computes rows w*8 .. w*8+7 of the tile (lane = f4 index).
// GEMM: 8x4 register tile per thread, W streamed in KCHUNK=16 slices.
// smem = 64*128*4 (xs) + 16*132*4 (wt) = 41216 B -> 5 blocks/SM.
// Also resets persistent-sync state for the next graph replay.
// ---------------------------------------------------------------------------
#define WT_STRIDE 132
#define KCHUNK 16
#define GROWS 64
#define GG_SMEM ((KCHUNK * WT_STRIDE + GROWS * 128) * 4)

__global__ __launch_bounds__(256)
void k_gg(const float4* __restrict__ x4, const float* __restrict__ W,
          const float* __restrict__ b, float* __restrict__ out, int n) {
    extern __shared__ float sm[];
    float* wt = sm;                       // [KCHUNK][WT_STRIDE]
    float* xs = sm + KCHUNK * WT_STRIDE;  // [GROWS][128]

    int tid  = threadIdx.x;
    int lane = tid & 31;
    int wrp  = tid >> 5;
    int row0 = blockIdx.x * GROWS;

    // reset build-kernel sync state for the next launch (deterministic)
    if (blockIdx.x == 0) {
        if (tid < 4) g_sctr[tid] = 0;
        for (int i = tid; i < MAX_BLD; i += 256) g_flag[i] = 0;
    }

    // ---- gather phase: each warp produces 8 rows of the h tile ----
#pragma unroll 1
    for (int j = 0; j < 8; j++) {
        int r = wrp * 8 + j;
        int v = row0 + r;
        float4 h = make_float4(0.f, 0.f, 0.f, 0.f);
        if (v < n) {
            int deg  = g_deg[v];
            int base = g_off[v] - deg;
            float4 acc = make_float4(0.f, 0.f, 0.f, 0.f);
            int e = 0;
            int deg4 = deg & ~3;
            for (; e < deg4; e += 4) {
                int nb0 = __ldg(&g_adj[base + e]);
                int nb1 = __ldg(&g_adj[base + e + 1]);
                int nb2 = __ldg(&g_adj[base + e + 2]);
                int nb3 = __ldg(&g_adj[base + e + 3]);
                float w0 = __ldg(&g_dinv[nb0]);
                float w1 = __ldg(&g_dinv[nb1]);
                float w2 = __ldg(&g_dinv[nb2]);
                float w3 = __ldg(&g_dinv[nb3]);
                float4 v0 = __ldg(x4 + (size_t)nb0 * 32 + lane);
                float4 v1 = __ldg(x4 + (size_t)nb1 * 32 + lane);
                float4 v2 = __ldg(x4 + (size_t)nb2 * 32 + lane);
                float4 v3 = __ldg(x4 + (size_t)nb3 * 32 + lane);
                acc.x += w0 * v0.x + w1 * v1.x + w2 * v2.x + w3 * v3.x;
                acc.y += w0 * v0.y + w1 * v1.y + w2 * v2.y + w3 * v3.y;
                acc.z += w0 * v0.z + w1 * v1.z + w2 * v2.z + w3 * v3.z;
                acc.w += w0 * v0.w + w1 * v1.w + w2 * v2.w + w3 * v3.w;
            }
            for (; e < deg; e++) {
                int nb = __ldg(&g_adj[base + e]);
                float w = __ldg(&g_dinv[nb]);
                float4 vv = __ldg(x4 + (size_t)nb * 32 + lane);
                acc.x += w * vv.x; acc.y += w * vv.y;
                acc.z += w * vv.z; acc.w += w * vv.w;
            }
            float dv = g_dinv[v];
            float4 xv = __ldg(x4 + (size_t)v * 32 + lane);
            h.x = xv.x + dv * acc.x;
            h.y = xv.y + dv * acc.y;
            h.z = xv.z + dv * acc.z;
            h.w = xv.w + dv * acc.w;
        }
        *(float4*)&xs[r * 128 + lane * 4] = h;
    }

    // ---- GEMM phase ----
    int r0 = wrp * 8;
    int c0 = lane * 4;

    float acc[8][4];
#pragma unroll
    for (int r = 0; r < 8; r++)
#pragma unroll
        for (int c = 0; c < 4; c++) acc[r][c] = 0.0f;

    for (int k0 = 0; k0 < 128; k0 += KCHUNK) {
        __syncthreads();
        for (int i = tid; i < 128 * KCHUNK; i += 256) {
            int j  = i >> 4;
            int kk = i & (KCHUNK - 1);
            wt[kk * WT_STRIDE + j] = W[j * 128 + k0 + kk];
        }
        __syncthreads();

#pragma unroll
        for (int kk = 0; kk < KCHUNK; kk++) {
            int k = k0 + kk;
            float4 wv = *(const float4*)(wt + kk * WT_STRIDE + c0);
#pragma unroll
            for (int r = 0; r < 8; r++) {
                float a = xs[(r0 + r) * 128 + k];
                acc[r][0] += a * wv.x;
                acc[r][1] += a * wv.y;
                acc[r][2] += a * wv.z;
                acc[r][3] += a * wv.w;
            }
        }
    }

    float4 bv = *(const float4*)(b + c0);
#pragma unroll
    for (int r = 0; r < 8; r++) {
        int row = row0 + r0 + r;
        if (row < n) {
            float4 o;
            o.x = fmaxf(acc[r][0] + bv.x, 0.0f);
            o.y = fmaxf(acc[r][1] + bv.y, 0.0f);
            o.z = fmaxf(acc[r][2] + bv.z, 0.0f);
            o.w = fmaxf(acc[r][3] + bv.w, 0.0f);
            *(float4*)(out + (size_t)row * DFEAT + c0) = o;
        }
    }
}

// ---------------------------------------------------------------------------
// kernel_launch
// inputs: 0=x [N,128] f32, 1=edge_index [2,E] int32/int64, 2=W [128,128], 3=b [128]
// ---------------------------------------------------------------------------
extern "C" void kernel_launch(void* const* d_in, const int* in_sizes, int n_in,
                              void* d_out, int out_size) {
    const float* x    = (const float*)d_in[0];
    const int*   ei_w = (const int*)d_in[1];
    const float* W    = (const float*)d_in[2];
    const float* b    = (const float*)d_in[3];
    float*       out  = (float*)d_out;

    int n = in_sizes[0] / DFEAT;
    int E = in_sizes[1] / 2;

    int nb = BLD_NB;
    int need = (n + BLD_BLK - 1) / BLD_BLK;
    if (need > nb) nb = need;            // n > 227K would need more (not here)

    k_build<<<nb, BLD_BLK>>>(ei_w, n, E, nb);
    k_gg<<<(n + GROWS - 1) / GROWS, 256, GG_SMEM>>>((const float4*)x, W, b, out, n);
}